// round 15
// baseline (speedup 1.0000x reference)
#include <cuda_runtime.h>
#include <cuda_bf16.h>
#include <cuda_fp16.h>
#include <math.h>
#include <stdint.h>

#define Bn   8192
#define In   512
#define Hn   1024
#define Rn   64
#define FourH 4096
#define SLAB (Bn * 64)

// ------------------------------------------------------------------
// Device scratch
// ------------------------------------------------------------------
__device__ __half g_Pf[Bn * 128];          // P fp16 [B][128]
__device__ __half g_Vt[128 * FourH];       // Vt fp16 [k][4096], col = j*4+g
__device__ __half g_Pph[12 * SLAB];        // proj partial slabs (fp16)
__device__ float g_cfx[FourH];
__device__ float g_cfh[FourH];
__device__ float g_bias[FourH];

// ------------------------------------------------------------------
// PTX helpers
// ------------------------------------------------------------------
__device__ __forceinline__ uint32_t smem_u32(const void* p) {
    return (uint32_t)__cvta_generic_to_shared(p);
}
__device__ __forceinline__ void ldsm_x4(uint32_t* r, uint32_t a) {
    asm volatile("ldmatrix.sync.aligned.m8n8.x4.shared.b16 {%0,%1,%2,%3}, [%4];"
        : "=r"(r[0]), "=r"(r[1]), "=r"(r[2]), "=r"(r[3]) : "r"(a));
}
__device__ __forceinline__ void ldsm_x4_t(uint32_t* r, uint32_t a) {
    asm volatile("ldmatrix.sync.aligned.m8n8.x4.trans.shared.b16 {%0,%1,%2,%3}, [%4];"
        : "=r"(r[0]), "=r"(r[1]), "=r"(r[2]), "=r"(r[3]) : "r"(a));
}
// fp16 mma
__device__ __forceinline__ void mma16816h(float* c, const uint32_t* a,
                                          uint32_t b0, uint32_t b1) {
    asm volatile("mma.sync.aligned.m16n8k16.row.col.f32.f16.f16.f32 "
        "{%0,%1,%2,%3}, {%4,%5,%6,%7}, {%8,%9}, {%0,%1,%2,%3};"
        : "+f"(c[0]), "+f"(c[1]), "+f"(c[2]), "+f"(c[3])
        : "r"(a[0]), "r"(a[1]), "r"(a[2]), "r"(a[3]), "r"(b0), "r"(b1));
}
__device__ __forceinline__ uint32_t pack_f16(__half lo16, __half hi16) {
    return (uint32_t)__half_as_ushort(lo16) |
           ((uint32_t)__half_as_ushort(hi16) << 16);
}
__device__ __forceinline__ void cpa16(uint32_t dst, const void* src) {
    asm volatile("cp.async.cg.shared.global [%0], [%1], 16;"
        :: "r"(dst), "l"(src) : "memory");
}
#define CP_COMMIT() asm volatile("cp.async.commit_group;" ::: "memory")
#define CP_WAIT1()  asm volatile("cp.async.wait_group 1;" ::: "memory")
#define CP_WAIT0()  asm volatile("cp.async.wait_group 0;" ::: "memory")

// fast activations via MUFU.TANH (sm_75+): 1 MUFU each
__device__ __forceinline__ float tanha(float v) {
    float r;
    asm("tanh.approx.f32 %0, %1;" : "=f"(r) : "f"(v));
    return r;
}
__device__ __forceinline__ float fsigmoid(float v) {
    return fmaf(0.5f, tanha(0.5f * v), 0.5f);
}

// ------------------------------------------------------------------
// Fused prep: Vt fp16 + (first FourH threads also do coef/bias)
// ------------------------------------------------------------------
__global__ void prep_kernel(const float* __restrict__ u_x,
                            const float* __restrict__ u_h,
                            const float* __restrict__ v_x,
                            const float* __restrict__ v_h,
                            const float* __restrict__ b_x,
                            const float* __restrict__ b_h) {
    int idx = blockIdx.x * blockDim.x + threadIdx.x;
    {
        int r   = idx >> 12;
        int col = idx & (FourH - 1);
        int j = col >> 2;
        int g = col & 3;
        int row4h = g * Hn + j;
        float v = (r < 64) ? v_x[row4h * Rn + r] : v_h[row4h * Rn + (r - 64)];
        g_Vt[idx] = __float2half(v);
    }
    if (idx < FourH) {
        int j = idx >> 2;
        int g = idx & 3;
        int row4h = g * Hn + j;
        float cx = 0.f;
        if (j < In) {
            const float* uxr = u_x + j * Rn;
            const float* vxr = v_x + row4h * Rn;
            #pragma unroll 8
            for (int r = 0; r < Rn; r++) cx += uxr[r] * vxr[r];
        }
        float ch = 0.f;
        {
            const float* uhr = u_h + j * Rn;
            const float* vhr = v_h + row4h * Rn;
            #pragma unroll 8
            for (int r = 0; r < Rn; r++) ch += uhr[r] * vhr[r];
        }
        g_cfx[idx]  = cx;
        g_cfh[idx]  = ch;
        g_bias[idx] = b_x[row4h] + b_h[row4h];
    }
}

// ------------------------------------------------------------------
// Projection split-K partials (fp16 single-pass HMMA, fp16 out).
// 12 slices of K=128: slices 0-3 = x@u_x, slices 4-11 = h@u_h.
// CTA: 128 rows x 64 cols, 2 serial k-chunks of 64.
// 8 warps (4m x 2n), warp tile 32x32.
// ------------------------------------------------------------------
__global__ __launch_bounds__(256)
void proj_part_kernel(const float* __restrict__ x, const float* __restrict__ u_x,
                      const float* __restrict__ h, const float* __restrict__ u_h) {
    __shared__ __half sA[128 * 72];
    __shared__ __half sB[64 * 72];

    int tid = threadIdx.x;
    int lane = tid & 31, w = tid >> 5;
    int wm = w >> 1, wn = w & 1;

    int slice = blockIdx.y;
    bool isX = (slice < 4);
    const float* A = isX ? x   : h;
    const float* U = isX ? u_x : u_h;
    int K      = isX ? In : Hn;
    int kBase  = (isX ? slice : (slice - 4)) * 128;
    int rowBase = blockIdx.x * 128;
    __half* outSlab = g_Pph + (size_t)slice * SLAB;

    float C[2][4][4];
    #pragma unroll
    for (int m = 0; m < 2; m++)
        #pragma unroll
        for (int n = 0; n < 4; n++)
            #pragma unroll
            for (int q = 0; q < 4; q++) C[m][n][q] = 0.f;

    #pragma unroll
    for (int kc = 0; kc < 2; kc++) {
        int k0 = kBase + kc * 64;
        // A: 128 rows x 64 k fp32 -> fp16 smem (2048 float4)
        #pragma unroll
        for (int p = 0; p < 8; p++) {
            int e = p * 256 + tid;
            int row = e >> 4, c4 = e & 15;
            float4 v = *(const float4*)(A + (size_t)(rowBase + row) * K + k0 + c4 * 4);
            uint2 hv;
            hv.x = pack_f16(__float2half(v.x), __float2half(v.y));
            hv.y = pack_f16(__float2half(v.z), __float2half(v.w));
            *(uint2*)&sA[row * 72 + c4 * 4] = hv;
        }
        // U: 64 k x 64 n fp32 -> fp16 smem (1024 float4)
        #pragma unroll
        for (int p = 0; p < 4; p++) {
            int e = p * 256 + tid;
            int row = e >> 4, c4 = e & 15;
            float4 u = *(const float4*)(U + (size_t)(k0 + row) * 64 + c4 * 4);
            uint2 hu;
            hu.x = pack_f16(__float2half(u.x), __float2half(u.y));
            hu.y = pack_f16(__float2half(u.z), __float2half(u.w));
            *(uint2*)&sB[row * 72 + c4 * 4] = hu;
        }
        __syncthreads();

        #pragma unroll
        for (int kk = 0; kk < 64; kk += 16) {
            uint32_t bF[4][2];
            #pragma unroll
            for (int p = 0; p < 2; p++) {
                int kr = kk + (lane & 15);
                int nc = wn * 32 + p * 16 + 8 * (lane >> 4);
                uint32_t r[4];
                ldsm_x4_t(r, smem_u32(&sB[kr * 72 + nc]));
                bF[2 * p][0] = r[0]; bF[2 * p][1] = r[1];
                bF[2 * p + 1][0] = r[2]; bF[2 * p + 1][1] = r[3];
            }
            #pragma unroll
            for (int m = 0; m < 2; m++) {
                uint32_t aF[4];
                int row = wm * 32 + m * 16 + (lane & 15);
                int col = kk + 8 * (lane >> 4);
                ldsm_x4(aF, smem_u32(&sA[row * 72 + col]));
                #pragma unroll
                for (int n = 0; n < 4; n++)
                    mma16816h(C[m][n], aF, bF[n][0], bF[n][1]);
            }
        }
        __syncthreads();
    }

    // write fp16 partial
    int quad = lane >> 2, a4 = lane & 3;
    #pragma unroll
    for (int n = 0; n < 4; n++) {
        int col = wn * 32 + n * 8 + a4 * 2;
        #pragma unroll
        for (int m = 0; m < 2; m++) {
            int r0 = rowBase + wm * 32 + m * 16 + quad;
            *(uint32_t*)&outSlab[(size_t)r0 * 64 + col] =
                pack_f16(__float2half(C[m][n][0]), __float2half(C[m][n][1]));
            *(uint32_t*)&outSlab[(size_t)(r0 + 8) * 64 + col] =
                pack_f16(__float2half(C[m][n][2]), __float2half(C[m][n][3]));
        }
    }
}

// ------------------------------------------------------------------
// Combine: sum fp16 partial slabs (4 for x-cols, 8 for h-cols), emit P fp16.
// ------------------------------------------------------------------
__global__ __launch_bounds__(256)
void combine_kernel() {
    int idx = blockIdx.x * 256 + threadIdx.x;     // 0 .. Bn*32-1
    int row = idx >> 5;
    int c4  = idx & 31;
    int col = c4 * 4;

    float4 v = make_float4(0.f, 0.f, 0.f, 0.f);
    if (col < 64) {
        const __half* p = g_Pph + (size_t)row * 64 + col;
        #pragma unroll
        for (int s = 0; s < 4; s++) {
            uint2 a = *(const uint2*)(p + (size_t)s * SLAB);
            float2 f0 = __half22float2(*reinterpret_cast<__half2*>(&a.x));
            float2 f1 = __half22float2(*reinterpret_cast<__half2*>(&a.y));
            v.x += f0.x; v.y += f0.y; v.z += f1.x; v.w += f1.y;
        }
    } else {
        const __half* p = g_Pph + 4 * (size_t)SLAB + (size_t)row * 64 + (col - 64);
        #pragma unroll
        for (int s = 0; s < 8; s++) {
            uint2 a = *(const uint2*)(p + (size_t)s * SLAB);
            float2 f0 = __half22float2(*reinterpret_cast<__half2*>(&a.x));
            float2 f1 = __half22float2(*reinterpret_cast<__half2*>(&a.y));
            v.x += f0.x; v.y += f0.y; v.z += f1.x; v.w += f1.y;
        }
    }

    uint2 w;
    w.x = pack_f16(__float2half(v.x), __float2half(v.y));
    w.y = pack_f16(__float2half(v.z), __float2half(v.w));
    *(uint2*)&g_Pf[(size_t)row * 128 + col] = w;
}

// ------------------------------------------------------------------
// Main GEMM (P @ Vt, K=128, fp16 single-pass) + coalesced epilogue.
// CTA tile M=128 x N=128, 512 thr, 16 warps (4m x 4n), warp 32x32.
// Two K=64 chunks, double-buffered, 3 barriers. 2 CTAs/SM.
// ------------------------------------------------------------------
#define AST 72
#define BST 136
#define U_A  0
#define U_B  (128 * AST)
#define STAGE_UNITS (128 * AST + 64 * BST)           // 17920 units = 35840 B
#define CST 132
#define SMEM_TOTAL (2 * STAGE_UNITS * 2)             // 71680 B (sC 67584 fits)

__global__ __launch_bounds__(512, 2)
void main_kernel(const float* __restrict__ x, const float* __restrict__ h,
                 const float* __restrict__ c,
                 const float* __restrict__ dia_x, const float* __restrict__ dia_h,
                 float* __restrict__ out) {
    extern __shared__ __half smh[];

    int tid = threadIdx.x;
    int lane = tid & 31, w = tid >> 5;
    int wm = w >> 2, wn = w & 3;
    int rowBase = blockIdx.y * 128;
    int colBase = blockIdx.x * 128;
    int j0 = colBase >> 2;
    bool ctaHasX = (j0 < In);

    uint32_t sbase = smem_u32(smh);

    auto load_chunk = [&](int k0, int stage) {
        uint32_t sb = sbase + stage * STAGE_UNITS * 2;
        #pragma unroll
        for (int t = 0; t < 2; t++) {
            int e = t * 512 + tid;
            int r = e >> 3, cc = e & 7;
            cpa16(sb + U_A * 2 + (r * AST + cc * 8) * 2,
                  g_Pf + (size_t)(rowBase + r) * 128 + k0 + cc * 8);
        }
        #pragma unroll
        for (int t = 0; t < 2; t++) {
            int e = t * 512 + tid;
            int kr = e >> 4, cc = e & 15;
            cpa16(sb + U_B * 2 + (kr * BST + cc * 8) * 2,
                  g_Vt + (size_t)(k0 + kr) * FourH + colBase + cc * 8);
        }
        CP_COMMIT();
    };

    float C[2][4][4];
    #pragma unroll
    for (int m = 0; m < 2; m++)
        #pragma unroll
        for (int n = 0; n < 4; n++)
            #pragma unroll
            for (int q = 0; q < 4; q++) C[m][n][q] = 0.f;

    load_chunk(0, 0);
    load_chunk(64, 1);

    #pragma unroll
    for (int ck = 0; ck < 2; ck++) {
        if (ck == 0) { CP_WAIT1(); } else { CP_WAIT0(); }
        __syncthreads();

        __half* sA = smh + ck * STAGE_UNITS + U_A;
        __half* sB = smh + ck * STAGE_UNITS + U_B;

        #pragma unroll
        for (int kk = 0; kk < 64; kk += 16) {
            uint32_t bF[4][2];
            #pragma unroll
            for (int p = 0; p < 2; p++) {
                int kr = kk + (lane & 15);
                int nc = wn * 32 + p * 16 + 8 * (lane >> 4);
                uint32_t r[4];
                ldsm_x4_t(r, smem_u32(&sB[kr * BST + nc]));
                bF[2 * p][0] = r[0]; bF[2 * p][1] = r[1];
                bF[2 * p + 1][0] = r[2]; bF[2 * p + 1][1] = r[3];
            }
            #pragma unroll
            for (int m = 0; m < 2; m++) {
                uint32_t aF[4];
                int row = wm * 32 + m * 16 + (lane & 15);
                int col = kk + 8 * (lane >> 4);
                ldsm_x4(aF, smem_u32(&sA[row * AST + col]));
                #pragma unroll
                for (int n = 0; n < 4; n++)
                    mma16816h(C[m][n], aF, bF[n][0], bF[n][1]);
            }
        }
    }
    __syncthreads();

    // ---------------- epilogue: stage C in smem, coalesced I/O ----------------
    float* sC = (float*)smh;
    int quad = lane >> 2, a4 = lane & 3;

    #pragma unroll
    for (int n = 0; n < 4; n++) {
        int col = wn * 32 + n * 8 + a4 * 2;
        #pragma unroll
        for (int m = 0; m < 2; m++) {
            int r0 = wm * 32 + m * 16 + quad;
            *(float2*)&sC[r0 * CST + col]       = make_float2(C[m][n][0], C[m][n][1]);
            *(float2*)&sC[(r0 + 8) * CST + col] = make_float2(C[m][n][2], C[m][n][3]);
        }
    }
    __syncthreads();

    int jl = tid & 31;
    int j  = j0 + jl;
    bool hasX = ctaHasX;

    float4 cfx = *(const float4*)(g_cfx  + (size_t)j * 4);
    float4 cfh = *(const float4*)(g_cfh  + (size_t)j * 4);
    float4 bs  = *(const float4*)(g_bias + (size_t)j * 4);
    float dxv = hasX ? dia_x[j] : 0.f;
    float dhv = dia_h[j];

    #pragma unroll
    for (int pass = 0; pass < 8; pass++) {
        int bl = pass * 16 + (tid >> 5);
        int b  = rowBase + bl;

        float4 g4 = *(const float4*)&sC[bl * CST + jl * 4];
        float xv = hasX ? x[(size_t)b * In + j] : 0.f;
        float hv = h[(size_t)b * Hn + j];
        float cv = c[(size_t)b * Hn + j];
        float z  = dxv * xv + dhv * hv;

        float gi = g4.x - xv * cfx.x - hv * cfh.x + bs.x + z;
        float gf = g4.y - xv * cfx.y - hv * cfh.y + bs.y + z;
        float go = g4.z - xv * cfx.z - hv * cfh.z + bs.z + z;
        float gn = g4.w - xv * cfx.w - hv * cfh.w + bs.w + z;

        float ig = fsigmoid(gi);
        float fg = fsigmoid(gf);
        float og = fsigmoid(go);
        float ng = tanha(gn);

        float cn = fg * cv + ig * ng;
        float hn = og * tanha(cn);

        out[(size_t)b * Hn + j]                   = hn;
        out[(size_t)Bn * Hn + (size_t)b * Hn + j] = cn;
    }
}

// ------------------------------------------------------------------
extern "C" void kernel_launch(void* const* d_in, const int* in_sizes, int n_in,
                              void* d_out, int out_size) {
    const float* x     = (const float*)d_in[0];
    const float* h     = (const float*)d_in[1];
    const float* c     = (const float*)d_in[2];
    const float* u_x   = (const float*)d_in[3];
    const float* u_h   = (const float*)d_in[4];
    const float* v_x   = (const float*)d_in[5];
    const float* v_h   = (const float*)d_in[6];
    const float* b_x   = (const float*)d_in[7];
    const float* b_h   = (const float*)d_in[8];
    const float* dia_x = (const float*)d_in[9];
    const float* dia_h = (const float*)d_in[10];
    float* out = (float*)d_out;

    prep_kernel<<<(128 * FourH) / 256, 256>>>(u_x, u_h, v_x, v_h, b_x, b_h);

    proj_part_kernel<<<dim3(Bn / 128, 12), 256>>>(x, u_x, h, u_h);
    combine_kernel<<<(Bn * 32) / 256, 256>>>();

    cudaFuncSetAttribute(main_kernel,
                         cudaFuncAttributeMaxDynamicSharedMemorySize, SMEM_TOTAL);
    dim3 grid(FourH / 128, Bn / 128);
    main_kernel<<<grid, 512, SMEM_TOTAL>>>(x, h, c, dia_x, dia_h, out);
}

// round 16
// speedup vs baseline: 1.4184x; 1.4184x over previous
#include <cuda_runtime.h>
#include <cuda_bf16.h>
#include <cuda_fp16.h>
#include <math.h>
#include <stdint.h>

#define Bn   8192
#define In   512
#define Hn   1024
#define Rn   64
#define FourH 4096
#define SLAB (Bn * 64)

// ------------------------------------------------------------------
// Device scratch
// ------------------------------------------------------------------
__device__ __half g_Pf[Bn * 128];          // P fp16 [B][128]
__device__ __half g_Vt[128 * FourH];       // Vt fp16 [k][4096], col = j*4+g
__device__ __half g_Pph[12 * SLAB];        // proj partial slabs (fp16)
__device__ float g_cfx[FourH];
__device__ float g_cfh[FourH];
__device__ float g_bias[FourH];

// ------------------------------------------------------------------
// PTX helpers
// ------------------------------------------------------------------
__device__ __forceinline__ uint32_t smem_u32(const void* p) {
    return (uint32_t)__cvta_generic_to_shared(p);
}
__device__ __forceinline__ void ldsm_x4(uint32_t* r, uint32_t a) {
    asm volatile("ldmatrix.sync.aligned.m8n8.x4.shared.b16 {%0,%1,%2,%3}, [%4];"
        : "=r"(r[0]), "=r"(r[1]), "=r"(r[2]), "=r"(r[3]) : "r"(a));
}
__device__ __forceinline__ void ldsm_x4_t(uint32_t* r, uint32_t a) {
    asm volatile("ldmatrix.sync.aligned.m8n8.x4.trans.shared.b16 {%0,%1,%2,%3}, [%4];"
        : "=r"(r[0]), "=r"(r[1]), "=r"(r[2]), "=r"(r[3]) : "r"(a));
}
// fp16 mma
__device__ __forceinline__ void mma16816h(float* c, const uint32_t* a,
                                          uint32_t b0, uint32_t b1) {
    asm volatile("mma.sync.aligned.m16n8k16.row.col.f32.f16.f16.f32 "
        "{%0,%1,%2,%3}, {%4,%5,%6,%7}, {%8,%9}, {%0,%1,%2,%3};"
        : "+f"(c[0]), "+f"(c[1]), "+f"(c[2]), "+f"(c[3])
        : "r"(a[0]), "r"(a[1]), "r"(a[2]), "r"(a[3]), "r"(b0), "r"(b1));
}
__device__ __forceinline__ uint32_t pack_f16(__half lo16, __half hi16) {
    return (uint32_t)__half_as_ushort(lo16) |
           ((uint32_t)__half_as_ushort(hi16) << 16);
}
__device__ __forceinline__ void cpa16(uint32_t dst, const void* src) {
    asm volatile("cp.async.cg.shared.global [%0], [%1], 16;"
        :: "r"(dst), "l"(src) : "memory");
}
#define CP_COMMIT() asm volatile("cp.async.commit_group;" ::: "memory")
#define CP_WAIT1()  asm volatile("cp.async.wait_group 1;" ::: "memory")
#define CP_WAIT0()  asm volatile("cp.async.wait_group 0;" ::: "memory")

// fast activations via MUFU.TANH (sm_75+): 1 MUFU each
__device__ __forceinline__ float tanha(float v) {
    float r;
    asm("tanh.approx.f32 %0, %1;" : "=f"(r) : "f"(v));
    return r;
}
__device__ __forceinline__ float fsigmoid(float v) {
    return fmaf(0.5f, tanha(0.5f * v), 0.5f);
}

// ------------------------------------------------------------------
// Fused prep: Vt fp16 + (first FourH threads also do coef/bias)
// ------------------------------------------------------------------
__global__ void prep_kernel(const float* __restrict__ u_x,
                            const float* __restrict__ u_h,
                            const float* __restrict__ v_x,
                            const float* __restrict__ v_h,
                            const float* __restrict__ b_x,
                            const float* __restrict__ b_h) {
    int idx = blockIdx.x * blockDim.x + threadIdx.x;
    {
        int r   = idx >> 12;
        int col = idx & (FourH - 1);
        int j = col >> 2;
        int g = col & 3;
        int row4h = g * Hn + j;
        float v = (r < 64) ? v_x[row4h * Rn + r] : v_h[row4h * Rn + (r - 64)];
        g_Vt[idx] = __float2half(v);
    }
    if (idx < FourH) {
        int j = idx >> 2;
        int g = idx & 3;
        int row4h = g * Hn + j;
        float cx = 0.f;
        if (j < In) {
            const float* uxr = u_x + j * Rn;
            const float* vxr = v_x + row4h * Rn;
            #pragma unroll 8
            for (int r = 0; r < Rn; r++) cx += uxr[r] * vxr[r];
        }
        float ch = 0.f;
        {
            const float* uhr = u_h + j * Rn;
            const float* vhr = v_h + row4h * Rn;
            #pragma unroll 8
            for (int r = 0; r < Rn; r++) ch += uhr[r] * vhr[r];
        }
        g_cfx[idx]  = cx;
        g_cfh[idx]  = ch;
        g_bias[idx] = b_x[row4h] + b_h[row4h];
    }
}

// ------------------------------------------------------------------
// Projection split-K partials (fp16 single-pass HMMA, fp16 out).
// 12 slices of K=128: slices 0-3 = x@u_x, slices 4-11 = h@u_h.
// CTA: 64 rows x 64 cols, 2 serial k-chunks of 64. Warps 4m x 2n, warp 16x32.
// (R13-proven shape; only the partial-output dtype changed to fp16.)
// ------------------------------------------------------------------
__global__ __launch_bounds__(256)
void proj_part_kernel(const float* __restrict__ x, const float* __restrict__ u_x,
                      const float* __restrict__ h, const float* __restrict__ u_h) {
    __shared__ __half sA[64 * 72];
    __shared__ __half sB[64 * 72];

    int tid = threadIdx.x;
    int lane = tid & 31, w = tid >> 5;
    int wm = w >> 1, wn = w & 1;

    int slice = blockIdx.y;
    bool isX = (slice < 4);
    const float* A = isX ? x   : h;
    const float* U = isX ? u_x : u_h;
    int K      = isX ? In : Hn;
    int kBase  = (isX ? slice : (slice - 4)) * 128;
    int rowBase = blockIdx.x * 64;
    __half* outSlab = g_Pph + (size_t)slice * SLAB;

    float C[4][4];
    #pragma unroll
    for (int n = 0; n < 4; n++)
        #pragma unroll
        for (int q = 0; q < 4; q++) C[n][q] = 0.f;

    #pragma unroll
    for (int kc = 0; kc < 2; kc++) {
        int k0 = kBase + kc * 64;
        #pragma unroll
        for (int p = 0; p < 4; p++) {
            int e = p * 256 + tid;
            int row = e >> 4, c4 = e & 15;
            float4 v = *(const float4*)(A + (size_t)(rowBase + row) * K + k0 + c4 * 4);
            uint2 hv;
            hv.x = pack_f16(__float2half(v.x), __float2half(v.y));
            hv.y = pack_f16(__float2half(v.z), __float2half(v.w));
            *(uint2*)&sA[row * 72 + c4 * 4] = hv;
            float4 u = *(const float4*)(U + (size_t)(k0 + row) * 64 + c4 * 4);
            uint2 hu;
            hu.x = pack_f16(__float2half(u.x), __float2half(u.y));
            hu.y = pack_f16(__float2half(u.z), __float2half(u.w));
            *(uint2*)&sB[row * 72 + c4 * 4] = hu;
        }
        __syncthreads();

        #pragma unroll
        for (int kk = 0; kk < 64; kk += 16) {
            uint32_t aF[4];
            {
                int row = wm * 16 + (lane & 15);
                int col = kk + 8 * (lane >> 4);
                ldsm_x4(aF, smem_u32(&sA[row * 72 + col]));
            }
            uint32_t bF[4][2];
            #pragma unroll
            for (int p = 0; p < 2; p++) {
                int kr = kk + (lane & 15);
                int nc = wn * 32 + p * 16 + 8 * (lane >> 4);
                uint32_t r[4];
                ldsm_x4_t(r, smem_u32(&sB[kr * 72 + nc]));
                bF[2 * p][0] = r[0]; bF[2 * p][1] = r[1];
                bF[2 * p + 1][0] = r[2]; bF[2 * p + 1][1] = r[3];
            }
            #pragma unroll
            for (int n = 0; n < 4; n++)
                mma16816h(C[n], aF, bF[n][0], bF[n][1]);
        }
        __syncthreads();
    }

    // write fp16 partial
    int quad = lane >> 2, a4 = lane & 3;
    #pragma unroll
    for (int n = 0; n < 4; n++) {
        int col = wn * 32 + n * 8 + a4 * 2;
        int r0  = rowBase + wm * 16 + quad;
        *(uint32_t*)&outSlab[(size_t)r0 * 64 + col] =
            pack_f16(__float2half(C[n][0]), __float2half(C[n][1]));
        *(uint32_t*)&outSlab[(size_t)(r0 + 8) * 64 + col] =
            pack_f16(__float2half(C[n][2]), __float2half(C[n][3]));
    }
}

// ------------------------------------------------------------------
// Combine: sum fp16 partial slabs (4 for x-cols, 8 for h-cols), emit P fp16.
// ------------------------------------------------------------------
__global__ __launch_bounds__(256)
void combine_kernel() {
    int idx = blockIdx.x * 256 + threadIdx.x;     // 0 .. Bn*32-1
    int row = idx >> 5;
    int c4  = idx & 31;
    int col = c4 * 4;

    float4 v = make_float4(0.f, 0.f, 0.f, 0.f);
    if (col < 64) {
        const __half* p = g_Pph + (size_t)row * 64 + col;
        #pragma unroll
        for (int s = 0; s < 4; s++) {
            uint2 a = *(const uint2*)(p + (size_t)s * SLAB);
            float2 f0 = __half22float2(*reinterpret_cast<__half2*>(&a.x));
            float2 f1 = __half22float2(*reinterpret_cast<__half2*>(&a.y));
            v.x += f0.x; v.y += f0.y; v.z += f1.x; v.w += f1.y;
        }
    } else {
        const __half* p = g_Pph + 4 * (size_t)SLAB + (size_t)row * 64 + (col - 64);
        #pragma unroll
        for (int s = 0; s < 8; s++) {
            uint2 a = *(const uint2*)(p + (size_t)s * SLAB);
            float2 f0 = __half22float2(*reinterpret_cast<__half2*>(&a.x));
            float2 f1 = __half22float2(*reinterpret_cast<__half2*>(&a.y));
            v.x += f0.x; v.y += f0.y; v.z += f1.x; v.w += f1.y;
        }
    }

    uint2 w;
    w.x = pack_f16(__float2half(v.x), __float2half(v.y));
    w.y = pack_f16(__float2half(v.z), __float2half(v.w));
    *(uint2*)&g_Pf[(size_t)row * 128 + col] = w;
}

// ------------------------------------------------------------------
// Main GEMM (P @ Vt, K=128, fp16 single-pass) + coalesced epilogue.
// CTA tile M=128 x N=128, 512 thr, 16 warps (4m x 4n), warp 32x32.
// Two K=64 chunks, double-buffered, 3 barriers. 2 CTAs/SM. (R13-proven.)
// ------------------------------------------------------------------
#define AST 72
#define BST 136
#define U_A  0
#define U_B  (128 * AST)
#define STAGE_UNITS (128 * AST + 64 * BST)           // 17920 units = 35840 B
#define CST 132
#define SMEM_TOTAL (2 * STAGE_UNITS * 2)             // 71680 B (sC 67584 fits)

__global__ __launch_bounds__(512, 2)
void main_kernel(const float* __restrict__ x, const float* __restrict__ h,
                 const float* __restrict__ c,
                 const float* __restrict__ dia_x, const float* __restrict__ dia_h,
                 float* __restrict__ out) {
    extern __shared__ __half smh[];

    int tid = threadIdx.x;
    int lane = tid & 31, w = tid >> 5;
    int wm = w >> 2, wn = w & 3;
    int rowBase = blockIdx.y * 128;
    int colBase = blockIdx.x * 128;
    int j0 = colBase >> 2;
    bool ctaHasX = (j0 < In);

    uint32_t sbase = smem_u32(smh);

    auto load_chunk = [&](int k0, int stage) {
        uint32_t sb = sbase + stage * STAGE_UNITS * 2;
        #pragma unroll
        for (int t = 0; t < 2; t++) {
            int e = t * 512 + tid;
            int r = e >> 3, cc = e & 7;
            cpa16(sb + U_A * 2 + (r * AST + cc * 8) * 2,
                  g_Pf + (size_t)(rowBase + r) * 128 + k0 + cc * 8);
        }
        #pragma unroll
        for (int t = 0; t < 2; t++) {
            int e = t * 512 + tid;
            int kr = e >> 4, cc = e & 15;
            cpa16(sb + U_B * 2 + (kr * BST + cc * 8) * 2,
                  g_Vt + (size_t)(k0 + kr) * FourH + colBase + cc * 8);
        }
        CP_COMMIT();
    };

    float C[2][4][4];
    #pragma unroll
    for (int m = 0; m < 2; m++)
        #pragma unroll
        for (int n = 0; n < 4; n++)
            #pragma unroll
            for (int q = 0; q < 4; q++) C[m][n][q] = 0.f;

    load_chunk(0, 0);
    load_chunk(64, 1);

    #pragma unroll
    for (int ck = 0; ck < 2; ck++) {
        if (ck == 0) { CP_WAIT1(); } else { CP_WAIT0(); }
        __syncthreads();

        __half* sA = smh + ck * STAGE_UNITS + U_A;
        __half* sB = smh + ck * STAGE_UNITS + U_B;

        #pragma unroll
        for (int kk = 0; kk < 64; kk += 16) {
            uint32_t bF[4][2];
            #pragma unroll
            for (int p = 0; p < 2; p++) {
                int kr = kk + (lane & 15);
                int nc = wn * 32 + p * 16 + 8 * (lane >> 4);
                uint32_t r[4];
                ldsm_x4_t(r, smem_u32(&sB[kr * BST + nc]));
                bF[2 * p][0] = r[0]; bF[2 * p][1] = r[1];
                bF[2 * p + 1][0] = r[2]; bF[2 * p + 1][1] = r[3];
            }
            #pragma unroll
            for (int m = 0; m < 2; m++) {
                uint32_t aF[4];
                int row = wm * 32 + m * 16 + (lane & 15);
                int col = kk + 8 * (lane >> 4);
                ldsm_x4(aF, smem_u32(&sA[row * AST + col]));
                #pragma unroll
                for (int n = 0; n < 4; n++)
                    mma16816h(C[m][n], aF, bF[n][0], bF[n][1]);
            }
        }
    }
    __syncthreads();

    // ---------------- epilogue: stage C in smem, coalesced I/O ----------------
    float* sC = (float*)smh;
    int quad = lane >> 2, a4 = lane & 3;

    #pragma unroll
    for (int n = 0; n < 4; n++) {
        int col = wn * 32 + n * 8 + a4 * 2;
        #pragma unroll
        for (int m = 0; m < 2; m++) {
            int r0 = wm * 32 + m * 16 + quad;
            *(float2*)&sC[r0 * CST + col]       = make_float2(C[m][n][0], C[m][n][1]);
            *(float2*)&sC[(r0 + 8) * CST + col] = make_float2(C[m][n][2], C[m][n][3]);
        }
    }
    __syncthreads();

    int jl = tid & 31;
    int j  = j0 + jl;
    bool hasX = ctaHasX;

    float4 cfx = *(const float4*)(g_cfx  + (size_t)j * 4);
    float4 cfh = *(const float4*)(g_cfh  + (size_t)j * 4);
    float4 bs  = *(const float4*)(g_bias + (size_t)j * 4);
    float dxv = hasX ? dia_x[j] : 0.f;
    float dhv = dia_h[j];

    #pragma unroll
    for (int pass = 0; pass < 8; pass++) {
        int bl = pass * 16 + (tid >> 5);
        int b  = rowBase + bl;

        float4 g4 = *(const float4*)&sC[bl * CST + jl * 4];
        float xv = hasX ? x[(size_t)b * In + j] : 0.f;
        float hv = h[(size_t)b * Hn + j];
        float cv = c[(size_t)b * Hn + j];
        float z  = dxv * xv + dhv * hv;

        float gi = g4.x - xv * cfx.x - hv * cfh.x + bs.x + z;
        float gf = g4.y - xv * cfx.y - hv * cfh.y + bs.y + z;
        float go = g4.z - xv * cfx.z - hv * cfh.z + bs.z + z;
        float gn = g4.w - xv * cfx.w - hv * cfh.w + bs.w + z;

        float ig = fsigmoid(gi);
        float fg = fsigmoid(gf);
        float og = fsigmoid(go);
        float ng = tanha(gn);

        float cn = fg * cv + ig * ng;
        float hn = og * tanha(cn);

        out[(size_t)b * Hn + j]                   = hn;
        out[(size_t)Bn * Hn + (size_t)b * Hn + j] = cn;
    }
}

// ------------------------------------------------------------------
extern "C" void kernel_launch(void* const* d_in, const int* in_sizes, int n_in,
                              void* d_out, int out_size) {
    const float* x     = (const float*)d_in[0];
    const float* h     = (const float*)d_in[1];
    const float* c     = (const float*)d_in[2];
    const float* u_x   = (const float*)d_in[3];
    const float* u_h   = (const float*)d_in[4];
    const float* v_x   = (const float*)d_in[5];
    const float* v_h   = (const float*)d_in[6];
    const float* b_x   = (const float*)d_in[7];
    const float* b_h   = (const float*)d_in[8];
    const float* dia_x = (const float*)d_in[9];
    const float* dia_h = (const float*)d_in[10];
    float* out = (float*)d_out;

    prep_kernel<<<(128 * FourH) / 256, 256>>>(u_x, u_h, v_x, v_h, b_x, b_h);

    proj_part_kernel<<<dim3(Bn / 64, 12), 256>>>(x, u_x, h, u_h);
    combine_kernel<<<(Bn * 32) / 256, 256>>>();

    cudaFuncSetAttribute(main_kernel,
                         cudaFuncAttributeMaxDynamicSharedMemorySize, SMEM_TOTAL);
    dim3 grid(FourH / 128, Bn / 128);
    main_kernel<<<grid, 512, SMEM_TOTAL>>>(x, h, c, dia_x, dia_h, out);
}